// round 7
// baseline (speedup 1.0000x reference)
#include <cuda_runtime.h>
#include <math.h>

#define EPSV 1e-5f

// packed fp32x2 helpers (SASS FFMA2 — only reachable via PTX fma.rn.f32x2)
#define FMA2(d, a, b, c) \
    asm("fma.rn.f32x2 %0, %1, %2, %3;" : "=l"(d) : "l"(a), "l"(b), "l"(c))
#define BCAST2(d, f) \
    asm("mov.b64 %0, {%1, %1};" : "=l"(d) : "r"(__float_as_uint(f)))
#define UNPACK2(lo, hi, v) \
    { unsigned _ulo, _uhi; \
      asm("mov.b64 {%0, %1}, %2;" : "=r"(_ulo), "=r"(_uhi) : "l"(v)); \
      lo = __uint_as_float(_ulo); hi = __uint_as_float(_uhi); }

// ------------------------------------------------------------------
// scratch (static device globals — no allocation anywhere)
// ------------------------------------------------------------------
__device__ float g_om[4*27*4096];        // [b][o][h*w]  (offset conv output, pre-bias)
__device__ float g_wdcn_t[9*256*256];    // [k][ci][co]
__device__ float g_wup_t[16*256*256];    // [kh][kw][ci][co]
__device__ float g_out1[4*256*4096];     // raw DCN output (pre-BN1), NCHW
__device__ float g_sum1[256], g_sq1[256], g_scale1[256], g_shift1[256];
__device__ float g_sum2[256], g_sq2[256], g_scale2[256], g_shift2[256];

// ------------------------------------------------------------------
// tiny prep kernels
// ------------------------------------------------------------------
__global__ void k_zero_stats() {
    int t = threadIdx.x;
    if (t < 256) { g_sum1[t] = 0.f; g_sq1[t] = 0.f; g_sum2[t] = 0.f; g_sq2[t] = 0.f; }
}

__global__ void k_zero_om() {
    int i = blockIdx.x * 1024 + threadIdx.x;
    if (i < 4*27*4096) g_om[i] = 0.f;
}

// w_dcn [co][ci][3][3] -> [k][ci][co]
__global__ void k_wdcn_t(const float* __restrict__ w) {
    int i = blockIdx.x * 256 + threadIdx.x;
    if (i < 9*256*256) {
        int co  = i / 2304;
        int rem = i - co * 2304;
        int ci  = rem / 9;
        int k   = rem - ci * 9;
        g_wdcn_t[(k*256 + ci)*256 + co] = w[i];
    }
}

// w_up [ci][co][4][4] -> [kh][kw][ci][co]
__global__ void k_wup_t(const float* __restrict__ w) {
    int i = blockIdx.x * 256 + threadIdx.x;
    if (i < 16*256*256) {
        int ci = i >> 12;
        int co = (i >> 4) & 255;
        int rs = i & 15;
        g_wup_t[(rs*256 + ci)*256 + co] = w[i];
    }
}

// ------------------------------------------------------------------
// offset conv (FFMA2, o-pair-major weights): g_om += conv3x3(x, w_off)
// grid 256: (b, 4-row tile, 64-ci group); 256 threads = 256 pixels
// ------------------------------------------------------------------
__global__ void __launch_bounds__(256) k_offset(const float* __restrict__ x,
                                                const float* __restrict__ w_off) {
    __shared__ __align__(16) float s_w2[16*9*28];   // [cl][tap][o padded to 28] = 16KB
    int bid = blockIdx.x;
    int cig = bid & 3;
    int bh  = bid >> 2;
    int b   = bh >> 4;
    int h0  = (bh & 15) * 4;
    int tid = threadIdx.x;
    int h = h0 + (tid >> 6);
    int w = tid & 63;

    unsigned long long acc2[14];
#pragma unroll
    for (int c2 = 0; c2 < 14; c2++) acc2[c2] = 0ull;

    for (int cc = 0; cc < 4; cc++) {       // 4 chunks of 16 ci
        __syncthreads();
        for (int s = tid; s < 4032; s += 256) {
            int cl = s / 252; int r = s - cl*252; int tap = r / 28; int o = r - tap*28;
            int ci = cig*64 + cc*16 + cl;
            s_w2[s] = (o < 27) ? w_off[(o*256 + ci)*9 + tap] : 0.f;
        }
        __syncthreads();
        for (int cl = 0; cl < 16; cl++) {
            int ci = cig*64 + cc*16 + cl;
            const float* xb = x + (((size_t)b*256 + ci) << 12);
            float xv[9];
#pragma unroll
            for (int ki = 0; ki < 3; ki++)
#pragma unroll
                for (int kj = 0; kj < 3; kj++) {
                    int yy = h + ki - 1, xx = w + kj - 1;
                    xv[ki*3+kj] = (yy >= 0 && yy < 64 && xx >= 0 && xx < 64)
                                  ? xb[(yy << 6) + xx] : 0.f;
                }
#pragma unroll
            for (int tap = 0; tap < 9; tap++) {
                unsigned long long xt;
                BCAST2(xt, xv[tap]);
                const float* wp = &s_w2[(cl*9 + tap)*28];
#pragma unroll
                for (int q = 0; q < 7; q++) {
                    ulonglong2 pq = *(const ulonglong2*)(wp + 4*q);
                    FMA2(acc2[2*q],   pq.x, xt, acc2[2*q]);
                    FMA2(acc2[2*q+1], pq.y, xt, acc2[2*q+1]);
                }
            }
        }
    }
    float acc[28];
#pragma unroll
    for (int c2 = 0; c2 < 14; c2++) {
        float lo, hi;
        UNPACK2(lo, hi, acc2[c2]);
        acc[2*c2] = lo; acc[2*c2+1] = hi;
    }
    int p = (h << 6) + w;
#pragma unroll
    for (int o = 0; o < 27; o++)
        atomicAdd(&g_om[((b*27 + o) << 12) + p], acc[o]);
}

// ------------------------------------------------------------------
// DCN: bilinear sample + mask + per-pixel GEMM (FFMA2, dup-pair s_val),
// BN1 stats. grid 512: (b, 32-pixel tile). 256 threads = 32 cog x 8 pxg.
// ------------------------------------------------------------------
__global__ void __launch_bounds__(256, 2) k_dcn(const float* __restrict__ x,
                                                const float* __restrict__ b_off,
                                                const float* __restrict__ b_dcn) {
    __shared__ int   s_idx[4*288];
    __shared__ float s_wt[4*288];
    __shared__ __align__(16) float s_val[16*9*32*2];   // duplicated pairs, 36.9KB

    int bid = blockIdx.x;
    int b   = bid >> 7;
    int px0 = (bid & 127) * 32;
    int tid = threadIdx.x;

    // per-pixel sample metadata (shared across all 256 channels)
    for (int s = tid; s < 288; s += 256) {
        int k  = s >> 5;
        int px = s & 31;
        int p  = px0 + px;
        int h  = p >> 6, w = p & 63;
        const float* omb = g_om + ((size_t)(b*27) << 12);
        float dy = omb[(k << 12) + p]        + b_off[k];
        float dx = omb[((9 + k) << 12) + p]  + b_off[9 + k];
        float mz = omb[((18 + k) << 12) + p] + b_off[18 + k];
        float m  = 1.f / (1.f + expf(-mz));
        float py  = dy + (float)h + (float)(k / 3 - 1);
        float pxx = dx + (float)w + (float)(k % 3 - 1);
        float y0f = floorf(py), x0f = floorf(pxx);
        float wy = py - y0f, wx = pxx - x0f;
        int y0 = (int)y0f, x0 = (int)x0f;
        float cw[4] = {(1.f - wy)*(1.f - wx), (1.f - wy)*wx, wy*(1.f - wx), wy*wx};
#pragma unroll
        for (int c = 0; c < 4; c++) {
            int yy = y0 + (c >> 1), xx = x0 + (c & 1);
            bool v = (yy >= 0 && yy < 64 && xx >= 0 && xx < 64);
            int yc = min(max(yy, 0), 63), xc = min(max(xx, 0), 63);
            s_idx[c*288 + s] = (yc << 6) + xc;
            s_wt[c*288 + s]  = v ? cw[c] * m : 0.f;
        }
    }
    __syncthreads();

    int co0 = (tid >> 3) * 8;     // 32 co-groups of 8 (4 packed pairs)
    int pp0 = (tid & 7) * 4;      // 8 px-groups of 4
    unsigned long long acc2[4][4];
#pragma unroll
    for (int c2 = 0; c2 < 4; c2++)
#pragma unroll
        for (int j = 0; j < 4; j++) acc2[c2][j] = 0ull;

    for (int cc = 0; cc < 16; cc++) {
        // gather stage: 16 ci x 288 samples, stored as duplicated pairs
        for (int t = tid; t < 4608; t += 256) {
            int cl = t / 288;
            int s  = t - cl * 288;
            int ci = cc*16 + cl;
            const float* xp = x + (((size_t)b*256 + ci) << 12);
            float v = s_wt[s]       * xp[s_idx[s]]
                    + s_wt[288 + s] * xp[s_idx[288 + s]]
                    + s_wt[576 + s] * xp[s_idx[576 + s]]
                    + s_wt[864 + s] * xp[s_idx[864 + s]];
            s_val[t*2] = v; s_val[t*2 + 1] = v;
        }
        __syncthreads();
        // GEMM stage (FFMA2; inputs via LDS.64 of dup pairs, no MOVs)
        for (int cl = 0; cl < 16; cl++) {
            int ci = cc*16 + cl;
#pragma unroll
            for (int k = 0; k < 9; k++) {
                const float* wr = g_wdcn_t + (((k << 8) + ci) << 8) + co0;
                ulonglong2 p0 = *(const ulonglong2*)wr;
                ulonglong2 p1 = *(const ulonglong2*)(wr + 4);
                unsigned long long w2[4] = {p0.x, p0.y, p1.x, p1.y};
                int vb = 2*((cl*9 + k)*32 + pp0);
                unsigned long long v2[4];
#pragma unroll
                for (int j = 0; j < 4; j++)
                    v2[j] = *(const unsigned long long*)&s_val[vb + 2*j];
#pragma unroll
                for (int c2 = 0; c2 < 4; c2++)
#pragma unroll
                    for (int j = 0; j < 4; j++)
                        FMA2(acc2[c2][j], w2[c2], v2[j], acc2[c2][j]);
            }
        }
        __syncthreads();
    }

    float acc[8][4];
#pragma unroll
    for (int c2 = 0; c2 < 4; c2++)
#pragma unroll
        for (int j = 0; j < 4; j++) {
            float lo, hi;
            UNPACK2(lo, hi, acc2[c2][j]);
            acc[2*c2][j] = lo; acc[2*c2+1][j] = hi;
        }

    // epilogue: bias, store raw out1, BN1 partial sums
    float psum[8], psq[8];
#pragma unroll
    for (int c = 0; c < 8; c++) {
        int co = co0 + c;
        float bd = b_dcn[co];
        float4 o;
        o.x = acc[c][0] + bd; o.y = acc[c][1] + bd;
        o.z = acc[c][2] + bd; o.w = acc[c][3] + bd;
        *(float4*)&g_out1[(((size_t)b*256 + co) << 12) + px0 + pp0] = o;
        psum[c] = o.x + o.y + o.z + o.w;
        psq[c]  = o.x*o.x + o.y*o.y + o.z*o.z + o.w*o.w;
    }
    int pxg = tid & 7;
#pragma unroll
    for (int c = 0; c < 8; c++) {
        s_val[(co0 + c)*8 + pxg]        = psum[c];
        s_val[2048 + (co0 + c)*8 + pxg] = psq[c];
    }
    __syncthreads();
    {
        float a = 0.f, q = 0.f;
#pragma unroll
        for (int g = 0; g < 8; g++) {
            a += s_val[tid*8 + g];
            q += s_val[2048 + tid*8 + g];
        }
        atomicAdd(&g_sum1[tid], a);
        atomicAdd(&g_sq1[tid],  q);
    }
}

// ------------------------------------------------------------------
// BN parameter kernels
// ------------------------------------------------------------------
__global__ void k_bn1(const float* __restrict__ gam, const float* __restrict__ bet) {
    int t = threadIdx.x;
    float m = g_sum1[t] * (1.f/16384.f);
    float v = g_sq1[t] * (1.f/16384.f) - m*m;
    float sc = gam[t] * rsqrtf(v + EPSV);
    g_scale1[t] = sc;
    g_shift1[t] = bet[t] - m*sc;
}
__global__ void k_bn2(const float* __restrict__ gam, const float* __restrict__ bet) {
    int t = threadIdx.x;
    float m = g_sum2[t] * (1.f/65536.f);
    float v = g_sq2[t] * (1.f/65536.f) - m*m;
    float sc = gam[t] * rsqrtf(v + EPSV);
    g_scale2[t] = sc;
    g_shift2[t] = bet[t] - m*sc;
}

// ------------------------------------------------------------------
// ConvTranspose (4x4, stride 2, pad 2), FFMA2 with smem-staged weights and
// dup-pair inputs; fused relu(BN1) on input; raw output + BN2 stats.
// grid 1024: (b, oy, ox-parity); 256 threads = 32 cog x 8 pxg.
// ------------------------------------------------------------------
__global__ void __launch_bounds__(256, 2) k_convt(float* __restrict__ out) {
    __shared__ __align__(16) float s_w[4*8*256];     // [rr*2+kws][cl][co], 32KB
    __shared__ __align__(16) float s_in[8*2*66*2];   // dup pairs, 8.25KB
    float* s_red = s_w;                              // reuse after main loop

    int bid = blockIdx.x;
    int b   = bid >> 8;
    int r   = bid & 255;
    int oy  = r >> 1;
    int par = r & 1;
    int tid = threadIdx.x;
    int co0 = (tid >> 3) * 8;
    int pxg = tid & 7;

    int kh0, kh1, ih0, ih1;
    if (oy & 1) { kh0 = 0; ih0 = (oy + 1) >> 1; kh1 = 2; ih1 = (oy - 1) >> 1; }
    else        { kh0 = 1; ih0 = oy >> 1;        kh1 = 3; ih1 = (oy >> 1) - 1; }
    bool v0 = (ih0 >= 0 && ih0 < 64);
    bool v1 = (ih1 >= 0 && ih1 < 64);
    int kw0, kw1, dmin;
    if (par) { kw0 = 0; kw1 = 2; dmin = 0;  }
    else     { kw0 = 1; kw1 = 3; dmin = -1; }

    unsigned long long acc2[4][8];
#pragma unroll
    for (int c2 = 0; c2 < 4; c2++)
#pragma unroll
        for (int j = 0; j < 8; j++) acc2[c2][j] = 0ull;

    for (int cc = 0; cc < 32; cc++) {
        __syncthreads();
        // stage weights for this chunk: 4 taps x 8 ci x 256 co
        for (int t = tid; t < 2048; t += 256) {
            int idx  = t * 4;
            int slot = idx >> 11;
            int rem  = idx & 2047;
            int cl   = rem >> 8;
            int co   = rem & 255;
            int rr   = slot >> 1, kws = slot & 1;
            int kh   = rr ? kh1 : kh0;
            int kw   = kws ? kw1 : kw0;
            int ci   = cc*8 + cl;
            float4 v = *(const float4*)&g_wup_t[((((kh<<2)+kw)*256 + ci) << 8) + co];
            *(float4*)&s_w[idx] = v;
        }
        // stage inputs (relu(BN1(out1))) as duplicated pairs
        for (int t = tid; t < 1056; t += 256) {
            int cl = t / 132;
            int q  = t - cl*132;
            int rr = q / 66;
            int ii = q - rr*66 - 1;
            int ci = cc*8 + cl;
            int ih = rr ? ih1 : ih0;
            bool vr = rr ? v1 : v0;
            float val = 0.f;
            if (vr && ii >= 0 && ii < 64) {
                float z = g_out1[(((size_t)b*256 + ci) << 12) + (ih << 6) + ii];
                z = z * g_scale1[ci] + g_shift1[ci];
                val = fmaxf(z, 0.f);
            }
            s_in[t*2] = val; s_in[t*2 + 1] = val;
        }
        __syncthreads();
        for (int cl = 0; cl < 8; cl++) {
#pragma unroll
            for (int rr = 0; rr < 2; rr++) {
                int base2 = ((cl*2 + rr)*66 + 1 + dmin + pxg) * 2;
                unsigned long long iv[8];
                // kw0 set multiplies column +1
#pragma unroll
                for (int jj = 0; jj < 8; jj++)
                    iv[jj] = *(const unsigned long long*)&s_in[base2 + 2 + 16*jj];
                {
                    const float* wr = &s_w[(((rr<<1)+0)*8 + cl)*256 + co0];
                    ulonglong2 p0 = *(const ulonglong2*)wr;
                    ulonglong2 p1 = *(const ulonglong2*)(wr + 4);
                    unsigned long long w2[4] = {p0.x, p0.y, p1.x, p1.y};
#pragma unroll
                    for (int c2 = 0; c2 < 4; c2++)
#pragma unroll
                        for (int jj = 0; jj < 8; jj++)
                            FMA2(acc2[c2][jj], w2[c2], iv[jj], acc2[c2][jj]);
                }
                // kw1 set multiplies column +0
#pragma unroll
                for (int jj = 0; jj < 8; jj++)
                    iv[jj] = *(const unsigned long long*)&s_in[base2 + 16*jj];
                {
                    const float* wr = &s_w[(((rr<<1)+1)*8 + cl)*256 + co0];
                    ulonglong2 p0 = *(const ulonglong2*)wr;
                    ulonglong2 p1 = *(const ulonglong2*)(wr + 4);
                    unsigned long long w2[4] = {p0.x, p0.y, p1.x, p1.y};
#pragma unroll
                    for (int c2 = 0; c2 < 4; c2++)
#pragma unroll
                        for (int jj = 0; jj < 8; jj++)
                            FMA2(acc2[c2][jj], w2[c2], iv[jj], acc2[c2][jj]);
                }
            }
        }
    }

    float acc[8][8];
#pragma unroll
    for (int c2 = 0; c2 < 4; c2++)
#pragma unroll
        for (int jj = 0; jj < 8; jj++) {
            float lo, hi;
            UNPACK2(lo, hi, acc2[c2][jj]);
            acc[2*c2][jj] = lo; acc[2*c2+1][jj] = hi;
        }

    // store raw output
#pragma unroll
    for (int c = 0; c < 8; c++) {
        int co = co0 + c;
        float* op = out + (((size_t)b*256 + co) << 14) + (oy << 7) + par;
#pragma unroll
        for (int jj = 0; jj < 8; jj++)
            op[(pxg + 8*jj) << 1] = acc[c][jj];
    }

    // BN2 partial sums (s_red aliases s_w; safe after sync)
    __syncthreads();
#pragma unroll
    for (int c = 0; c < 8; c++) {
        float a = 0.f;
#pragma unroll
        for (int jj = 0; jj < 8; jj++) a += acc[c][jj];
        s_red[(co0 + c)*8 + pxg] = a;
    }
    __syncthreads();
    {
        float a = 0.f;
#pragma unroll
        for (int g = 0; g < 8; g++) a += s_red[tid*8 + g];
        atomicAdd(&g_sum2[tid], a);
    }
    __syncthreads();
#pragma unroll
    for (int c = 0; c < 8; c++) {
        float q = 0.f;
#pragma unroll
        for (int jj = 0; jj < 8; jj++) q += acc[c][jj]*acc[c][jj];
        s_red[(co0 + c)*8 + pxg] = q;
    }
    __syncthreads();
    {
        float q = 0.f;
#pragma unroll
        for (int g = 0; g < 8; g++) q += s_red[tid*8 + g];
        atomicAdd(&g_sq2[tid], q);
    }
}

// ------------------------------------------------------------------
// final BN2 + ReLU, elementwise float4
// ------------------------------------------------------------------
__global__ void k_apply(float* __restrict__ out) {
    int i = blockIdx.x * 1024 + threadIdx.x;
    float4* o4 = (float4*)out;
    float4 v = o4[i];
    int c = (i >> 12) & 255;
    float sc = g_scale2[c], sh = g_shift2[c];
    v.x = fmaxf(fmaf(v.x, sc, sh), 0.f);
    v.y = fmaxf(fmaf(v.y, sc, sh), 0.f);
    v.z = fmaxf(fmaf(v.z, sc, sh), 0.f);
    v.w = fmaxf(fmaf(v.w, sc, sh), 0.f);
    o4[i] = v;
}

// ------------------------------------------------------------------
extern "C" void kernel_launch(void* const* d_in, const int* in_sizes, int n_in,
                              void* d_out, int out_size) {
    const float* x      = (const float*)d_in[0];
    const float* w_off  = (const float*)d_in[1];
    const float* b_off  = (const float*)d_in[2];
    const float* w_dcn  = (const float*)d_in[3];
    const float* b_dcn  = (const float*)d_in[4];
    const float* gamma1 = (const float*)d_in[5];
    const float* beta1  = (const float*)d_in[6];
    const float* w_up   = (const float*)d_in[7];
    const float* gamma2 = (const float*)d_in[8];
    const float* beta2  = (const float*)d_in[9];
    float* out = (float*)d_out;
    (void)in_sizes; (void)n_in; (void)out_size;

    k_zero_stats<<<1, 256>>>();
    k_zero_om<<<432, 1024>>>();
    k_wdcn_t<<<2304, 256>>>(w_dcn);
    k_wup_t<<<4096, 256>>>(w_up);
    k_offset<<<256, 256>>>(x, w_off);
    k_dcn<<<512, 256>>>(x, b_off, b_dcn);
    k_bn1<<<1, 256>>>(gamma1, beta1);
    k_convt<<<1024, 256>>>(out);
    k_bn2<<<1, 256>>>(gamma2, beta2);
    k_apply<<<4096, 1024>>>(out);
}

// round 8
// speedup vs baseline: 1.2709x; 1.2709x over previous
#include <cuda_runtime.h>
#include <math.h>

#define EPSV 1e-5f

// packed fp32x2 helpers (SASS FFMA2 — only reachable via PTX fma.rn.f32x2)
#define FMA2(d, a, b, c) \
    asm("fma.rn.f32x2 %0, %1, %2, %3;" : "=l"(d) : "l"(a), "l"(b), "l"(c))
#define BCAST2(d, f) \
    asm("mov.b64 %0, {%1, %1};" : "=l"(d) : "r"(__float_as_uint(f)))
#define UNPACK2(lo, hi, v) \
    { unsigned _ulo, _uhi; \
      asm("mov.b64 {%0, %1}, %2;" : "=r"(_ulo), "=r"(_uhi) : "l"(v)); \
      lo = __uint_as_float(_ulo); hi = __uint_as_float(_uhi); }

// ------------------------------------------------------------------
// scratch (static device globals — no allocation anywhere)
// ------------------------------------------------------------------
__device__ float g_om[4*27*4096];        // [b][o][h*w]
__device__ float g_wdcn_t[9*256*256];    // [k][ci][co]
__device__ float g_wup_t[16*256*256];    // [kh][kw][ci][co]
__device__ float g_out1[4*256*4096];     // raw DCN output (pre-BN1), NCHW
__device__ float g_sum1[256], g_sq1[256];
__device__ float g_sum2[256], g_sq2[256];

// ------------------------------------------------------------------
// fused prep: zero stats + zero g_om + both weight re-layouts
// grid 4096 x 256
// ------------------------------------------------------------------
__global__ void k_prep(const float* __restrict__ w_dcn,
                       const float* __restrict__ w_up) {
    int i = blockIdx.x * 256 + threadIdx.x;
    if (i < 256) { g_sum1[i] = 0.f; g_sq1[i] = 0.f; g_sum2[i] = 0.f; g_sq2[i] = 0.f; }
    if (i < 4*27*4096) g_om[i] = 0.f;
    if (i < 9*256*256) {
        int co  = i / 2304;
        int rem = i - co * 2304;
        int ci  = rem / 9;
        int k   = rem - ci * 9;
        g_wdcn_t[(k*256 + ci)*256 + co] = w_dcn[i];
    }
    if (i < 16*256*256) {
        int ci = i >> 12;
        int co = (i >> 4) & 255;
        int rs = i & 15;
        g_wup_t[(rs*256 + ci)*256 + co] = w_up[i];
    }
}

// ------------------------------------------------------------------
// offset conv: g_om += conv3x3(x, w_off)   (R4 body)
// ------------------------------------------------------------------
__global__ void __launch_bounds__(256) k_offset(const float* __restrict__ x,
                                                const float* __restrict__ w_off) {
    __shared__ __align__(16) float s_w[27*16*12];
    int bid = blockIdx.x;
    int cig = bid & 3;
    int bh  = bid >> 2;
    int b   = bh >> 4;
    int h0  = (bh & 15) * 4;
    int tid = threadIdx.x;
    int h = h0 + (tid >> 6);
    int w = tid & 63;

    float acc[27];
#pragma unroll
    for (int o = 0; o < 27; o++) acc[o] = 0.f;

    for (int cc = 0; cc < 4; cc++) {
        __syncthreads();
        for (int s = tid; s < 5184; s += 256) {
            int o = s / 192; int r2 = s - o*192; int cl = r2 / 12; int tap = r2 - cl*12;
            int ci = cig*64 + cc*16 + cl;
            s_w[s] = (tap < 9) ? w_off[(o*256 + ci)*9 + tap] : 0.f;
        }
        __syncthreads();
        for (int cl = 0; cl < 16; cl++) {
            int ci = cig*64 + cc*16 + cl;
            const float* xb = x + (((size_t)b*256 + ci) << 12);
            float xv[9];
#pragma unroll
            for (int ki = 0; ki < 3; ki++)
#pragma unroll
                for (int kj = 0; kj < 3; kj++) {
                    int yy = h + ki - 1, xx = w + kj - 1;
                    xv[ki*3+kj] = (yy >= 0 && yy < 64 && xx >= 0 && xx < 64)
                                  ? xb[(yy << 6) + xx] : 0.f;
                }
#pragma unroll
            for (int o = 0; o < 27; o++) {
                const float* wp = &s_w[(o*16 + cl)*12];
                float4 w0 = *(const float4*)wp;
                float4 w1 = *(const float4*)(wp + 4);
                float w8 = wp[8];
                acc[o] += w0.x*xv[0] + w0.y*xv[1] + w0.z*xv[2] + w0.w*xv[3]
                        + w1.x*xv[4] + w1.y*xv[5] + w1.z*xv[6] + w1.w*xv[7]
                        + w8*xv[8];
            }
        }
    }
    int p = (h << 6) + w;
#pragma unroll
    for (int o = 0; o < 27; o++)
        atomicAdd(&g_om[((b*27 + o) << 12) + p], acc[o]);
}

// ------------------------------------------------------------------
// DCN (R4 body): bilinear sample + mask + per-pixel GEMM (FFMA2), BN1 stats.
// grid 512: (b, 32-pixel tile). 256 threads.
// ------------------------------------------------------------------
__global__ void __launch_bounds__(256) k_dcn(const float* __restrict__ x,
                                             const float* __restrict__ b_off,
                                             const float* __restrict__ b_dcn) {
    __shared__ int   s_idx[4*288];
    __shared__ float s_wt[4*288];
    __shared__ __align__(16) float s_val[16*9*32];

    int bid = blockIdx.x;
    int b   = bid >> 7;
    int px0 = (bid & 127) * 32;
    int tid = threadIdx.x;

    for (int s = tid; s < 288; s += 256) {
        int k  = s >> 5;
        int px = s & 31;
        int p  = px0 + px;
        int h  = p >> 6, w = p & 63;
        const float* omb = g_om + ((size_t)(b*27) << 12);
        float dy = omb[(k << 12) + p]        + b_off[k];
        float dx = omb[((9 + k) << 12) + p]  + b_off[9 + k];
        float mz = omb[((18 + k) << 12) + p] + b_off[18 + k];
        float m  = 1.f / (1.f + expf(-mz));
        float py  = dy + (float)h + (float)(k / 3 - 1);
        float pxx = dx + (float)w + (float)(k % 3 - 1);
        float y0f = floorf(py), x0f = floorf(pxx);
        float wy = py - y0f, wx = pxx - x0f;
        int y0 = (int)y0f, x0 = (int)x0f;
        float cw[4] = {(1.f - wy)*(1.f - wx), (1.f - wy)*wx, wy*(1.f - wx), wy*wx};
#pragma unroll
        for (int c = 0; c < 4; c++) {
            int yy = y0 + (c >> 1), xx = x0 + (c & 1);
            bool v = (yy >= 0 && yy < 64 && xx >= 0 && xx < 64);
            int yc = min(max(yy, 0), 63), xc = min(max(xx, 0), 63);
            s_idx[c*288 + s] = (yc << 6) + xc;
            s_wt[c*288 + s]  = v ? cw[c] * m : 0.f;
        }
    }
    __syncthreads();

    int co0 = (tid >> 3) * 8;
    int pp0 = (tid & 7) * 4;
    unsigned long long acc2[4][4];
#pragma unroll
    for (int c2 = 0; c2 < 4; c2++)
#pragma unroll
        for (int j = 0; j < 4; j++) acc2[c2][j] = 0ull;

    for (int cc = 0; cc < 16; cc++) {
        for (int t = tid; t < 4608; t += 256) {
            int cl = t / 288;
            int s  = t - cl * 288;
            int ci = cc*16 + cl;
            const float* xp = x + (((size_t)b*256 + ci) << 12);
            float v = s_wt[s]       * xp[s_idx[s]]
                    + s_wt[288 + s] * xp[s_idx[288 + s]]
                    + s_wt[576 + s] * xp[s_idx[576 + s]]
                    + s_wt[864 + s] * xp[s_idx[864 + s]];
            s_val[cl*288 + s] = v;
        }
        __syncthreads();
        for (int cl = 0; cl < 16; cl++) {
            int ci = cc*16 + cl;
#pragma unroll 3
            for (int k = 0; k < 9; k++) {
                const ulonglong2* wp =
                    (const ulonglong2*)(g_wdcn_t + (((k << 8) + ci) << 8) + co0);
                ulonglong2 p0 = wp[0], p1 = wp[1];
                unsigned long long w2[4] = {p0.x, p0.y, p1.x, p1.y};
                float4 vq = *(const float4*)&s_val[(cl*9 + k)*32 + pp0];
                unsigned long long v2[4];
                BCAST2(v2[0], vq.x); BCAST2(v2[1], vq.y);
                BCAST2(v2[2], vq.z); BCAST2(v2[3], vq.w);
#pragma unroll
                for (int c2 = 0; c2 < 4; c2++)
#pragma unroll
                    for (int j = 0; j < 4; j++)
                        FMA2(acc2[c2][j], w2[c2], v2[j], acc2[c2][j]);
            }
        }
        __syncthreads();
    }

    float acc[8][4];
#pragma unroll
    for (int c2 = 0; c2 < 4; c2++)
#pragma unroll
        for (int j = 0; j < 4; j++) {
            float lo, hi;
            UNPACK2(lo, hi, acc2[c2][j]);
            acc[2*c2][j] = lo; acc[2*c2+1][j] = hi;
        }

    float psum[8], psq[8];
#pragma unroll
    for (int c = 0; c < 8; c++) {
        int co = co0 + c;
        float bd = b_dcn[co];
        float4 o;
        o.x = acc[c][0] + bd; o.y = acc[c][1] + bd;
        o.z = acc[c][2] + bd; o.w = acc[c][3] + bd;
        *(float4*)&g_out1[(((size_t)b*256 + co) << 12) + px0 + pp0] = o;
        psum[c] = o.x + o.y + o.z + o.w;
        psq[c]  = o.x*o.x + o.y*o.y + o.z*o.z + o.w*o.w;
    }
    int pxg = tid & 7;
#pragma unroll
    for (int c = 0; c < 8; c++) {
        s_val[(co0 + c)*8 + pxg]        = psum[c];
        s_val[2048 + (co0 + c)*8 + pxg] = psq[c];
    }
    __syncthreads();
    {
        float a = 0.f, q = 0.f;
#pragma unroll
        for (int g = 0; g < 8; g++) {
            a += s_val[tid*8 + g];
            q += s_val[2048 + tid*8 + g];
        }
        atomicAdd(&g_sum1[tid], a);
        atomicAdd(&g_sq1[tid],  q);
    }
}

// ------------------------------------------------------------------
// ConvTranspose (R4 body + BN1 params computed per-block in smem).
// grid 1024: (b, oy, ox-parity); 256 threads.
// ------------------------------------------------------------------
__global__ void __launch_bounds__(256) k_convt(float* __restrict__ out,
                                               const float* __restrict__ gamma1,
                                               const float* __restrict__ beta1) {
    __shared__ float s_in[8*2*66];
    __shared__ float s_red[2048];
    __shared__ float s_sc1[256], s_sh1[256];

    int bid = blockIdx.x;
    int b   = bid >> 8;
    int r   = bid & 255;
    int oy  = r >> 1;
    int par = r & 1;
    int tid = threadIdx.x;
    int co0 = (tid >> 3) * 8;
    int pxg = tid & 7;

    // BN1 params (redundant per block; deterministic)
    {
        float m = g_sum1[tid] * (1.f/16384.f);
        float v = g_sq1[tid] * (1.f/16384.f) - m*m;
        float sc = gamma1[tid] * rsqrtf(v + EPSV);
        s_sc1[tid] = sc;
        s_sh1[tid] = beta1[tid] - m*sc;
    }

    int kh0, kh1, ih0, ih1;
    if (oy & 1) { kh0 = 0; ih0 = (oy + 1) >> 1; kh1 = 2; ih1 = (oy - 1) >> 1; }
    else        { kh0 = 1; ih0 = oy >> 1;        kh1 = 3; ih1 = (oy >> 1) - 1; }
    bool v0 = (ih0 >= 0 && ih0 < 64);
    bool v1 = (ih1 >= 0 && ih1 < 64);
    int kw0, kw1, dmin;
    if (par) { kw0 = 0; kw1 = 2; dmin = 0;  }
    else     { kw0 = 1; kw1 = 3; dmin = -1; }

    unsigned long long acc2[4][8];
#pragma unroll
    for (int c2 = 0; c2 < 4; c2++)
#pragma unroll
        for (int j = 0; j < 8; j++) acc2[c2][j] = 0ull;

    for (int cc = 0; cc < 32; cc++) {
        __syncthreads();
        for (int t = tid; t < 1056; t += 256) {
            int cl = t / 132;
            int q  = t - cl*132;
            int rr = q / 66;
            int ii = q - rr*66 - 1;
            int ci = cc*8 + cl;
            int ih = rr ? ih1 : ih0;
            bool vr = rr ? v1 : v0;
            float val = 0.f;
            if (vr && ii >= 0 && ii < 64) {
                float z = g_out1[(((size_t)b*256 + ci) << 12) + (ih << 6) + ii];
                z = z * s_sc1[ci] + s_sh1[ci];
                val = fmaxf(z, 0.f);
            }
            s_in[t] = val;
        }
        __syncthreads();
        for (int cl = 0; cl < 8; cl++) {
            int ci = cc*8 + cl;
#pragma unroll
            for (int rr = 0; rr < 2; rr++) {
                int kh = rr ? kh1 : kh0;
                int base = (cl*2 + rr)*66 + 1 + dmin + pxg;
                unsigned long long ivA[8], ivB[8];
#pragma unroll
                for (int jj = 0; jj < 8; jj++) {
                    BCAST2(ivB[jj], s_in[base + 8*jj]);      // kw1 set
                    BCAST2(ivA[jj], s_in[base + 1 + 8*jj]);  // kw0 set
                }
                {
                    const ulonglong2* wp = (const ulonglong2*)
                        (g_wup_t + ((((kh << 2) + kw0)*256 + ci) << 8) + co0);
                    ulonglong2 p0 = wp[0], p1 = wp[1];
                    unsigned long long w2[4] = {p0.x, p0.y, p1.x, p1.y};
#pragma unroll
                    for (int c2 = 0; c2 < 4; c2++)
#pragma unroll
                        for (int jj = 0; jj < 8; jj++)
                            FMA2(acc2[c2][jj], w2[c2], ivA[jj], acc2[c2][jj]);
                }
                {
                    const ulonglong2* wp = (const ulonglong2*)
                        (g_wup_t + ((((kh << 2) + kw1)*256 + ci) << 8) + co0);
                    ulonglong2 p0 = wp[0], p1 = wp[1];
                    unsigned long long w2[4] = {p0.x, p0.y, p1.x, p1.y};
#pragma unroll
                    for (int c2 = 0; c2 < 4; c2++)
#pragma unroll
                        for (int jj = 0; jj < 8; jj++)
                            FMA2(acc2[c2][jj], w2[c2], ivB[jj], acc2[c2][jj]);
                }
            }
        }
    }

    float acc[8][8];
#pragma unroll
    for (int c2 = 0; c2 < 4; c2++)
#pragma unroll
        for (int jj = 0; jj < 8; jj++) {
            float lo, hi;
            UNPACK2(lo, hi, acc2[c2][jj]);
            acc[2*c2][jj] = lo; acc[2*c2+1][jj] = hi;
        }

#pragma unroll
    for (int c = 0; c < 8; c++) {
        int co = co0 + c;
        float* op = out + (((size_t)b*256 + co) << 14) + (oy << 7) + par;
#pragma unroll
        for (int jj = 0; jj < 8; jj++)
            op[(pxg + 8*jj) << 1] = acc[c][jj];
    }

    __syncthreads();
#pragma unroll
    for (int c = 0; c < 8; c++) {
        float a = 0.f;
#pragma unroll
        for (int jj = 0; jj < 8; jj++) a += acc[c][jj];
        s_red[(co0 + c)*8 + pxg] = a;
    }
    __syncthreads();
    {
        float a = 0.f;
#pragma unroll
        for (int g = 0; g < 8; g++) a += s_red[tid*8 + g];
        atomicAdd(&g_sum2[tid], a);
    }
    __syncthreads();
#pragma unroll
    for (int c = 0; c < 8; c++) {
        float q = 0.f;
#pragma unroll
        for (int jj = 0; jj < 8; jj++) q += acc[c][jj]*acc[c][jj];
        s_red[(co0 + c)*8 + pxg] = q;
    }
    __syncthreads();
    {
        float q = 0.f;
#pragma unroll
        for (int g = 0; g < 8; g++) q += s_red[tid*8 + g];
        atomicAdd(&g_sq2[tid], q);
    }
}

// ------------------------------------------------------------------
// final BN2 + ReLU (BN2 params computed per-block), elementwise float4
// ------------------------------------------------------------------
__global__ void k_apply(float* __restrict__ out,
                        const float* __restrict__ gamma2,
                        const float* __restrict__ beta2) {
    __shared__ float s_sc[256], s_sh[256];
    int t = threadIdx.x;
    if (t < 256) {
        float m = g_sum2[t] * (1.f/65536.f);
        float v = g_sq2[t] * (1.f/65536.f) - m*m;
        float sc = gamma2[t] * rsqrtf(v + EPSV);
        s_sc[t] = sc;
        s_sh[t] = beta2[t] - m*sc;
    }
    __syncthreads();
    int i = blockIdx.x * 1024 + t;
    float4* o4 = (float4*)out;
    float4 v = o4[i];
    int c = (i >> 12) & 255;
    float sc = s_sc[c], sh = s_sh[c];
    v.x = fmaxf(fmaf(v.x, sc, sh), 0.f);
    v.y = fmaxf(fmaf(v.y, sc, sh), 0.f);
    v.z = fmaxf(fmaf(v.z, sc, sh), 0.f);
    v.w = fmaxf(fmaf(v.w, sc, sh), 0.f);
    o4[i] = v;
}

// ------------------------------------------------------------------
extern "C" void kernel_launch(void* const* d_in, const int* in_sizes, int n_in,
                              void* d_out, int out_size) {
    const float* x      = (const float*)d_in[0];
    const float* w_off  = (const float*)d_in[1];
    const float* b_off  = (const float*)d_in[2];
    const float* w_dcn  = (const float*)d_in[3];
    const float* b_dcn  = (const float*)d_in[4];
    const float* gamma1 = (const float*)d_in[5];
    const float* beta1  = (const float*)d_in[6];
    const float* w_up   = (const float*)d_in[7];
    const float* gamma2 = (const float*)d_in[8];
    const float* beta2  = (const float*)d_in[9];
    float* out = (float*)d_out;
    (void)in_sizes; (void)n_in; (void)out_size;

    k_prep<<<4096, 256>>>(w_dcn, w_up);          // launch 1
    k_offset<<<256, 256>>>(x, w_off);            // launch 2
    k_dcn<<<512, 256>>>(x, b_off, b_dcn);        // launch 3
    k_convt<<<1024, 256>>>(out, gamma1, beta1);  // launch 4  <- ncu slot
    k_apply<<<4096, 1024>>>(out, gamma2, beta2); // launch 5
}